// round 2
// baseline (speedup 1.0000x reference)
#include <cuda_runtime.h>

// DotProductAttention: B=8, H=8, N=2048, D=64, fp32.
// logits = (Q K^T)/8 ; clipped = 10*tanh(logits) ; masked keys -> -1e10 ; softmax ; @V.
// R1: fix mask dtype (bool likely promoted to int32 by harness) via detection
//     pre-kernel + normalized __device__ mask buffer; add missing __syncwarp().

#define PAD 68   // smem row stride in floats (16B-aligned rows, conflict-spreading)

__device__ unsigned char g_mask[8 * 2048];   // normalized mask, 1 byte per (b, k)

// Detect whether the raw mask buffer is uint8 or int32 (values are all 0/1),
// then normalize into g_mask. int32 little-endian 0/1 words have every byte at
// index %4 != 0 equal to zero; a uint8 0/1 array almost surely does not.
__global__ void mask_normalize(const unsigned char* __restrict__ mraw, int n)
{
    __shared__ int is_u8;
    if (threadIdx.x == 0) {
        int nz = 0;
        for (int i = 0; i < 4096; i++) {          // stays within n bytes either way
            if ((i & 3) && mraw[i]) { nz = 1; break; }
        }
        is_u8 = nz;
    }
    __syncthreads();
    if (is_u8) {
        for (int i = threadIdx.x; i < n; i += blockDim.x)
            g_mask[i] = (mraw[i] != 0);
    } else {
        const int* mi = (const int*)mraw;
        for (int i = threadIdx.x; i < n; i += blockDim.x)
            g_mask[i] = (mi[i] != 0);
    }
}

__global__ void __launch_bounds__(128, 3)
attn_fwd(const float* __restrict__ Q, const float* __restrict__ K,
         const float* __restrict__ V, float* __restrict__ out)
{
    extern __shared__ float smem[];
    float* Qt = smem;                       // [64 d][PAD m]  (d-major Q tile)
    float* Kt = Qt + 64 * PAD;              // [64 d][PAD n]  (d-major K tile)
    float* Vs = Kt + 64 * PAD;              // [64 k][PAD d]  (row-major V tile)
    float* Ps = Vs + 64 * PAD;              // [64 m][PAD k]  (row-major P tile)
    unsigned char* msk = (unsigned char*)(Ps + 64 * PAD);  // [64]

    const int bh  = blockIdx.y;             // 0..63  (b*8 + h)
    const int b   = bh >> 3;
    const int q0  = blockIdx.x << 6;        // q tile start
    const int tid = threadIdx.x;
    const int warp = tid >> 5;
    const int lane = tid & 31;
    const int ty = lane >> 3;               // 0..3
    const int tx = lane & 7;                // 0..7
    const int m0 = (warp << 4) + (ty << 2); // this thread's 4 q-rows
    const int n0 = tx << 3;                 // this thread's 8 k-cols (and 8 d-cols for O)

    const float* Qg = Q + (((size_t)bh << 11) + q0) * 64;
    const float* Kg = K + ((size_t)bh << 11) * 64;
    const float* Vg = V + ((size_t)bh << 11) * 64;

    // ---- Load Q tile (64x64) transposed into Qt[d][m] ----
#pragma unroll
    for (int it = 0; it < 8; it++) {
        int idx = it * 128 + tid;           // 0..1023 float4 slots
        int r   = idx >> 4;                 // q row 0..63
        int c4  = (idx & 15) << 2;          // d 0,4,..,60
        float4 v = *(const float4*)(Qg + (r << 6) + c4);
        Qt[(c4 + 0) * PAD + r] = v.x;
        Qt[(c4 + 1) * PAD + r] = v.y;
        Qt[(c4 + 2) * PAD + r] = v.z;
        Qt[(c4 + 3) * PAD + r] = v.w;
    }

    // ---- Online-softmax state ----
    float mRow[4], lRow[4], Oa[4][8];
#pragma unroll
    for (int i = 0; i < 4; i++) {
        mRow[i] = -3.0e38f;
        lRow[i] = 0.0f;
#pragma unroll
        for (int j = 0; j < 8; j++) Oa[i][j] = 0.0f;
    }

    for (int kt = 0; kt < 32; kt++) {
        const int kv0 = kt << 6;
        __syncthreads();                    // prev iter's PV reads of Vs/Ps done

        // ---- Load K tile (transposed) + V tile (row-major) + mask ----
#pragma unroll
        for (int it = 0; it < 8; it++) {
            int idx = it * 128 + tid;
            int r   = idx >> 4;
            int c4  = (idx & 15) << 2;
            float4 kk = *(const float4*)(Kg + ((size_t)(kv0 + r) << 6) + c4);
            Kt[(c4 + 0) * PAD + r] = kk.x;
            Kt[(c4 + 1) * PAD + r] = kk.y;
            Kt[(c4 + 2) * PAD + r] = kk.z;
            Kt[(c4 + 3) * PAD + r] = kk.w;
            float4 vv = *(const float4*)(Vg + ((size_t)(kv0 + r) << 6) + c4);
            *(float4*)(Vs + r * PAD + c4) = vv;
        }
        if (tid < 64) msk[tid] = g_mask[(b << 11) + kv0 + tid];
        __syncthreads();

        // ---- S = Q K^T  (4x8 register tile per thread) ----
        float acc[4][8];
#pragma unroll
        for (int i = 0; i < 4; i++)
#pragma unroll
            for (int j = 0; j < 8; j++) acc[i][j] = 0.0f;

#pragma unroll 8
        for (int d = 0; d < 64; d++) {
            float4 a  = *(const float4*)(Qt + d * PAD + m0);
            float4 b0 = *(const float4*)(Kt + d * PAD + n0);
            float4 b1 = *(const float4*)(Kt + d * PAD + n0 + 4);
            float av[4] = {a.x, a.y, a.z, a.w};
            float bv[8] = {b0.x, b0.y, b0.z, b0.w, b1.x, b1.y, b1.z, b1.w};
#pragma unroll
            for (int i = 0; i < 4; i++)
#pragma unroll
                for (int j = 0; j < 8; j++)
                    acc[i][j] = fmaf(av[i], bv[j], acc[i][j]);
        }

        // ---- clip + mask + online softmax ----
        bool mk[8];
#pragma unroll
        for (int j = 0; j < 8; j++) mk[j] = (msk[n0 + j] != 0);

#pragma unroll
        for (int i = 0; i < 4; i++) {
            float c[8];
            float rmax = -3.0e38f;
#pragma unroll
            for (int j = 0; j < 8; j++) {
                float t  = acc[i][j] * 0.125f;                   // / sqrt(64)
                float e2 = __expf(2.0f * t);                     // tanh via exp
                float cv = 10.0f - __fdividef(20.0f, e2 + 1.0f); // 10*tanh(t)
                cv = mk[j] ? -1.0e10f : cv;
                c[j] = cv;
                rmax = fmaxf(rmax, cv);
            }
            rmax = fmaxf(rmax, __shfl_xor_sync(0xffffffffu, rmax, 1));
            rmax = fmaxf(rmax, __shfl_xor_sync(0xffffffffu, rmax, 2));
            rmax = fmaxf(rmax, __shfl_xor_sync(0xffffffffu, rmax, 4));
            float mnew = fmaxf(mRow[i], rmax);
            float sf   = __expf(mRow[i] - mnew);                 // exp(-huge)=0 on first tile
            mRow[i] = mnew;
            float rsum = 0.0f;
#pragma unroll
            for (int j = 0; j < 8; j++) {
                float e = __expf(c[j] - mnew);
                c[j] = e;
                rsum += e;
            }
            rsum += __shfl_xor_sync(0xffffffffu, rsum, 1);
            rsum += __shfl_xor_sync(0xffffffffu, rsum, 2);
            rsum += __shfl_xor_sync(0xffffffffu, rsum, 4);
            lRow[i] = lRow[i] * sf + rsum;
#pragma unroll
            for (int j = 0; j < 8; j++) Oa[i][j] *= sf;

            // stage P row (this warp's rows only)
            *(float4*)(Ps + (m0 + i) * PAD + n0)     = make_float4(c[0], c[1], c[2], c[3]);
            *(float4*)(Ps + (m0 + i) * PAD + n0 + 4) = make_float4(c[4], c[5], c[6], c[7]);
        }
        __syncwarp();   // Ps rows are assembled from 8 lanes; make writes visible

        // ---- O += P V  (p scalar broadcast loads, v float4) ----
#pragma unroll 4
        for (int k = 0; k < 64; k++) {
            float pv[4];
            pv[0] = Ps[(m0 + 0) * PAD + k];
            pv[1] = Ps[(m0 + 1) * PAD + k];
            pv[2] = Ps[(m0 + 2) * PAD + k];
            pv[3] = Ps[(m0 + 3) * PAD + k];
            float4 v0 = *(const float4*)(Vs + k * PAD + n0);
            float4 v1 = *(const float4*)(Vs + k * PAD + n0 + 4);
            float vv[8] = {v0.x, v0.y, v0.z, v0.w, v1.x, v1.y, v1.z, v1.w};
#pragma unroll
            for (int i = 0; i < 4; i++)
#pragma unroll
                for (int j = 0; j < 8; j++)
                    Oa[i][j] = fmaf(pv[i], vv[j], Oa[i][j]);
        }
    }

    // ---- epilogue: O /= l, store ----
#pragma unroll
    for (int i = 0; i < 4; i++) {
        float inv = 1.0f / lRow[i];
        float* og = out + (((size_t)bh << 11) + q0 + m0 + i) * 64 + n0;
        float4 o0 = make_float4(Oa[i][0] * inv, Oa[i][1] * inv, Oa[i][2] * inv, Oa[i][3] * inv);
        float4 o1 = make_float4(Oa[i][4] * inv, Oa[i][5] * inv, Oa[i][6] * inv, Oa[i][7] * inv);
        *(float4*)(og)     = o0;
        *(float4*)(og + 4) = o1;
    }
}

extern "C" void kernel_launch(void* const* d_in, const int* in_sizes, int n_in,
                              void* d_out, int out_size)
{
    const float* Q = (const float*)d_in[0];
    const float* K = (const float*)d_in[1];
    const float* V = (const float*)d_in[2];
    const unsigned char* mraw = (const unsigned char*)d_in[3];
    float* out = (float*)d_out;

    // Normalize mask (handles uint8 OR int32 harness conventions).
    mask_normalize<<<1, 256>>>(mraw, 8 * 2048);

    const size_t smem_bytes = 4 * 64 * PAD * sizeof(float) + 64;  // ~69.7 KB
    cudaFuncSetAttribute(attn_fwd, cudaFuncAttributeMaxDynamicSharedMemorySize,
                         (int)smem_bytes);

    dim3 grid(32, 64);   // (q tiles, B*H)
    attn_fwd<<<grid, 128, smem_bytes>>>(Q, K, V, out);
}

// round 4
// speedup vs baseline: 6.2537x; 6.2537x over previous
#include <cuda_runtime.h>
#include <cuda_bf16.h>
#include <cstdint>

// DotProductAttention B=8,H=8,N=2048,D=64 fp32 — R4.
// sm80-path flash attention: mma.sync.m16n8k16 bf16 (3-pass hi/lo split),
// fixed-max softmax (logits<=10 => max=10, no online rescale, O in C-frags),
// mask compaction (gathered unmasked keys, ~halves all per-key work).

#define SM_QHI 0
#define SM_QLO 8192
#define SM_KHI 16384
#define SM_KLO 24576
#define SM_VHI 32768
#define SM_VLO 40960
#define SM_TOTAL 49152

__device__ int g_cnt[8];
__device__ int g_idx[8][2048];

// ---- deterministic per-batch compaction of unmasked keys (mask==0) ----
__global__ void build_idx(const unsigned char* __restrict__ mraw)
{
    const int b = blockIdx.x;
    const int t = threadIdx.x;                 // 1024 threads
    __shared__ int wsum[32];

    // dtype detection (bool as uint8 vs int32): int32 0/1 words have all
    // bytes at idx%4!=0 equal to zero.
    int mynz = 0;
#pragma unroll
    for (int k = 0; k < 4; k++) {
        int i = t * 4 + k;
        if ((i & 3) && mraw[i]) mynz = 1;
    }
    const int is_u8 = __syncthreads_or(mynz);

    int m0, m1;
    if (is_u8) {
        m0 = mraw[b * 2048 + 2 * t];
        m1 = mraw[b * 2048 + 2 * t + 1];
    } else {
        const int* mi = (const int*)mraw;
        m0 = mi[b * 2048 + 2 * t];
        m1 = mi[b * 2048 + 2 * t + 1];
    }
    const int f0 = (m0 == 0), f1 = (m1 == 0);
    const int pair = f0 + f1;
    const int lane = t & 31, w = t >> 5;

    int sc = pair;                             // inclusive warp scan
#pragma unroll
    for (int d = 1; d < 32; d <<= 1) {
        int v = __shfl_up_sync(0xffffffffu, sc, d);
        if (lane >= d) sc += v;
    }
    if (lane == 31) wsum[w] = sc;
    __syncthreads();
    if (w == 0) {
        int s2 = wsum[lane];
#pragma unroll
        for (int d = 1; d < 32; d <<= 1) {
            int u = __shfl_up_sync(0xffffffffu, s2, d);
            if (lane >= d) s2 += u;
        }
        wsum[lane] = s2;
    }
    __syncthreads();
    int base = (w ? wsum[w - 1] : 0) + sc - pair;
    if (f0) g_idx[b][base++] = 2 * t;
    if (f1) g_idx[b][base] = 2 * t + 1;
    if (t == 0) g_cnt[b] = wsum[31];
}

// ---- helpers ----
__device__ __forceinline__ uint32_t smem_u32(const void* p) {
    uint32_t a;
    asm("{ .reg .u64 t; cvta.to.shared.u64 t, %1; cvt.u32.u64 %0, t; }" : "=r"(a) : "l"(p));
    return a;
}
__device__ __forceinline__ void mma_bf16(float* d, const uint32_t* a, const uint32_t* b) {
    asm volatile("mma.sync.aligned.m16n8k16.row.col.f32.bf16.bf16.f32 "
                 "{%0,%1,%2,%3}, {%4,%5,%6,%7}, {%8,%9}, {%0,%1,%2,%3};"
                 : "+f"(d[0]), "+f"(d[1]), "+f"(d[2]), "+f"(d[3])
                 : "r"(a[0]), "r"(a[1]), "r"(a[2]), "r"(a[3]), "r"(b[0]), "r"(b[1]));
}
__device__ __forceinline__ void ldsm2(uint32_t& r0, uint32_t& r1, uint32_t addr) {
    asm volatile("ldmatrix.sync.aligned.m8n8.x2.shared.b16 {%0,%1}, [%2];"
                 : "=r"(r0), "=r"(r1) : "r"(addr));
}
__device__ __forceinline__ void ldsm2t(uint32_t& r0, uint32_t& r1, uint32_t addr) {
    asm volatile("ldmatrix.sync.aligned.m8n8.x2.trans.shared.b16 {%0,%1}, [%2];"
                 : "=r"(r0), "=r"(r1) : "r"(addr));
}
__device__ __forceinline__ void ldsm4(uint32_t* r, uint32_t addr) {
    asm volatile("ldmatrix.sync.aligned.m8n8.x4.shared.b16 {%0,%1,%2,%3}, [%4];"
                 : "=r"(r[0]), "=r"(r[1]), "=r"(r[2]), "=r"(r[3]) : "r"(addr));
}
// pack (a -> low, b -> high) bf16 hi + residual lo
__device__ __forceinline__ void split2(float a, float b, uint32_t& hi, uint32_t& lo) {
    __nv_bfloat16 ha = __float2bfloat16(a), hb = __float2bfloat16(b);
    float ra = a - __bfloat162float(ha), rb = b - __bfloat162float(hb);
    __nv_bfloat16 la = __float2bfloat16(ra), lb = __float2bfloat16(rb);
    hi = (uint32_t)__bfloat16_as_ushort(ha) | ((uint32_t)__bfloat16_as_ushort(hb) << 16);
    lo = (uint32_t)__bfloat16_as_ushort(la) | ((uint32_t)__bfloat16_as_ushort(lb) << 16);
}

// ---- main kernel: 128 threads, 4 warps, 64 q-rows per CTA (16 per warp) ----
__global__ void __launch_bounds__(128)
attn_mma(const float* __restrict__ Q, const float* __restrict__ K,
         const float* __restrict__ V, float* __restrict__ out)
{
    extern __shared__ char smem[];
    const uint32_t sb = smem_u32(smem);

    const int tid  = threadIdx.x;
    const int warp = tid >> 5;
    const int lane = tid & 31;
    const int gid  = lane >> 2;        // row group 0..7
    const int tig  = lane & 3;         // 0..3
    const int R0   = warp << 4;        // warp's first q row in tile

    const int bh = blockIdx.y;
    const int b  = bh >> 3;
    const int q0 = blockIdx.x << 6;    // 64-row q tile

    const float* Qg = Q + (((size_t)bh << 11) + q0) * 64;
    const float* Kg = K + ((size_t)bh << 11) * 64;
    const float* Vg = V + ((size_t)bh << 11) * 64;
    const int*   idxb = g_idx[b];
    const int    cnt  = g_cnt[b];
    const int    ntiles = (cnt + 63) >> 6;

    // ---- prologue: Q -> smem (hi/lo bf16, 16B-chunk XOR swizzle) ----
#pragma unroll
    for (int it = 0; it < 8; it++) {
        int idx = it * 128 + tid;      // 1024 float4 slots: 64 rows x 16
        int r   = idx >> 4;
        int c4  = (idx & 15) << 2;
        float4 v = *(const float4*)(Qg + (r << 6) + c4);
        uint32_t h0, l0, h1, l1;
        split2(v.x, v.y, h0, l0);
        split2(v.z, v.w, h1, l1);
        uint32_t off = r * 128 + ((c4 * 2) ^ ((r & 7) << 4));
        *(uint2*)(smem + SM_QHI + off) = make_uint2(h0, h1);
        *(uint2*)(smem + SM_QLO + off) = make_uint2(l0, l1);
    }
    __syncthreads();

    // ---- load Q A-fragments (held in regs for the whole kernel) ----
    uint32_t qh[4][4], ql[4][4];
    {
        const int arow = R0 + (lane & 7) + ((lane >> 3) & 1) * 8;
        const int asw  = lane & 7;
#pragma unroll
        for (int kk = 0; kk < 4; kk++) {
            uint32_t off = arow * 128 + ((((2 * kk + (lane >> 4)) ^ asw)) << 4);
            ldsm4(qh[kk], sb + SM_QHI + off);
            ldsm4(ql[kk], sb + SM_QLO + off);
        }
    }

    float o[8][4];
#pragma unroll
    for (int j = 0; j < 8; j++)
#pragma unroll
        for (int e = 0; e < 4; e++) o[j][e] = 0.0f;
    float lsum_lo = 0.0f, lsum_hi = 0.0f;

    // per-lane ldmatrix address components
    const int krow = lane & 7;                 // K: rows 8j+krow, chunk 2kk+ksel
    const int ksel = (lane >> 3) & 1;
    const int vrow = (lane & 7) + ((lane >> 3) & 1) * 8;  // V: rows 16kk+vrow, chunk j

    for (int kt = 0; kt < ntiles; kt++) {
        const int kv0 = kt << 6;
        __syncthreads();                        // smem K/V reuse (prev tile readers done)

        // ---- gather-load K,V tiles (64 compacted keys) ----
#pragma unroll
        for (int it = 0; it < 8; it++) {
            int idx  = it * 128 + tid;          // 1024 slots
            int r    = idx >> 4;
            int c4   = (idx & 15) << 2;
            int slot = kv0 + r;
            int rg   = idxb[(slot < cnt) ? slot : 0];
            uint32_t off = r * 128 + ((c4 * 2) ^ ((r & 7) << 4));
            float4 kk = *(const float4*)(Kg + ((size_t)rg << 6) + c4);
            uint32_t h0, l0, h1, l1;
            split2(kk.x, kk.y, h0, l0);
            split2(kk.z, kk.w, h1, l1);
            *(uint2*)(smem + SM_KHI + off) = make_uint2(h0, h1);
            *(uint2*)(smem + SM_KLO + off) = make_uint2(l0, l1);
            float4 vv = *(const float4*)(Vg + ((size_t)rg << 6) + c4);
            split2(vv.x, vv.y, h0, l0);
            split2(vv.z, vv.w, h1, l1);
            *(uint2*)(smem + SM_VHI + off) = make_uint2(h0, h1);
            *(uint2*)(smem + SM_VLO + off) = make_uint2(l0, l1);
        }
        __syncthreads();

        // ---- S = Q K^T (3-pass split) ----
        float s[8][4];
#pragma unroll
        for (int j = 0; j < 8; j++) {
#pragma unroll
            for (int e = 0; e < 4; e++) s[j][e] = 0.0f;
#pragma unroll
            for (int kk = 0; kk < 4; kk++) {
                const int rr = 8 * j + krow;
                uint32_t off = rr * 128 + (((2 * kk + ksel) ^ krow) << 4);
                uint32_t kbh[2], kbl[2];
                ldsm2(kbh[0], kbh[1], sb + SM_KHI + off);
                ldsm2(kbl[0], kbl[1], sb + SM_KLO + off);
                mma_bf16(s[j], qh[kk], kbh);
                mma_bf16(s[j], qh[kk], kbl);
                mma_bf16(s[j], ql[kk], kbh);
            }
        }

        // ---- softmax transform: p = exp(10*tanh(s/8) - 10), invalid->0 ----
#pragma unroll
        for (int j = 0; j < 8; j++) {
#pragma unroll
            for (int e = 0; e < 4; e++) {
                int key_slot = kv0 + 8 * j + 2 * tig + (e & 1);
                float sv = s[j][e];
                float eu = __expf(0.25f * sv);
                float p  = __expf(-__fdividef(20.0f, eu + 1.0f));
                p = (key_slot < cnt) ? p : 0.0f;
                s[j][e] = p;
                if ((e & 2) == 0) lsum_lo += p; else lsum_hi += p;
            }
        }

        // ---- O += P V (3-pass split; P C-frags -> A-frags in regs) ----
#pragma unroll
        for (int kk = 0; kk < 4; kk++) {
            const int j0 = 2 * kk;
            uint32_t pah[4], pal[4];
            split2(s[j0][0],     s[j0][1],     pah[0], pal[0]);
            split2(s[j0][2],     s[j0][3],     pah[1], pal[1]);
            split2(s[j0 + 1][0], s[j0 + 1][1], pah[2], pal[2]);
            split2(s[j0 + 1][2], s[j0 + 1][3], pah[3], pal[3]);
#pragma unroll
            for (int j = 0; j < 8; j++) {
                const int rr = 16 * kk + vrow;
                uint32_t off = rr * 128 + ((j ^ (vrow & 7)) << 4);
                uint32_t vbh[2], vbl[2];
                ldsm2t(vbh[0], vbh[1], sb + SM_VHI + off);
                ldsm2t(vbl[0], vbl[1], sb + SM_VLO + off);
                mma_bf16(o[j], pah, vbh);
                mma_bf16(o[j], pah, vbl);
                mma_bf16(o[j], pal, vbh);
            }
        }
    }

    // ---- epilogue: reduce l over quad, scale, store ----
    lsum_lo += __shfl_xor_sync(0xffffffffu, lsum_lo, 1);
    lsum_lo += __shfl_xor_sync(0xffffffffu, lsum_lo, 2);
    lsum_hi += __shfl_xor_sync(0xffffffffu, lsum_hi, 1);
    lsum_hi += __shfl_xor_sync(0xffffffffu, lsum_hi, 2);
    const float inv_lo = 1.0f / lsum_lo;
    const float inv_hi = 1.0f / lsum_hi;

    const size_t row_lo = ((size_t)bh << 11) + q0 + R0 + gid;
    const size_t row_hi = row_lo + 8;
#pragma unroll
    for (int j = 0; j < 8; j++) {
        int col = 8 * j + 2 * tig;
        *(float2*)(out + row_lo * 64 + col) = make_float2(o[j][0] * inv_lo, o[j][1] * inv_lo);
        *(float2*)(out + row_hi * 64 + col) = make_float2(o[j][2] * inv_hi, o[j][3] * inv_hi);
    }
}

extern "C" void kernel_launch(void* const* d_in, const int* in_sizes, int n_in,
                              void* d_out, int out_size)
{
    const float* Q = (const float*)d_in[0];
    const float* K = (const float*)d_in[1];
    const float* V = (const float*)d_in[2];
    const unsigned char* mraw = (const unsigned char*)d_in[3];
    float* out = (float*)d_out;

    build_idx<<<8, 1024>>>(mraw);

    cudaFuncSetAttribute(attn_mma, cudaFuncAttributeMaxDynamicSharedMemorySize, SM_TOTAL);
    dim3 grid(32, 64);                  // (q tiles of 64, B*H)
    attn_mma<<<grid, 128, SM_TOTAL>>>(Q, K, V, out);
}

// round 6
// speedup vs baseline: 8.8224x; 1.4107x over previous
#include <cuda_runtime.h>
#include <cuda_bf16.h>
#include <cstdint>

// DotProductAttention B=8,H=8,N=2048,D=64 fp32 — R5.
// mma.sync bf16 3-pass flash attention, fixed-max softmax (logits<=10),
// mask compaction + K/V preconverted to bf16 hi/lo in compacted order,
// cp.async double-buffered K/V staging, 256-thread CTAs.

#define SM_QHI 0
#define SM_QLO 16384
#define SM_KV  32768            // 2 stages x 32KB: [KHI|KLO|VHI|VLO] 8KB each
#define STAGE  32768
#define SM_TOTAL (SM_KV + 2 * STAGE)   // 96KB

__device__ int g_cnt[8];
__device__ int g_idx[8][2048];
__device__ unsigned char KCH[1 << 24];   // 16MB each: [bh][slot][64 bf16]
__device__ unsigned char KCL[1 << 24];
__device__ unsigned char VCH[1 << 24];
__device__ unsigned char VCL[1 << 24];

// ---- pass 1: deterministic per-batch compaction of unmasked keys ----
__global__ void build_idx(const unsigned char* __restrict__ mraw)
{
    const int b = blockIdx.x;
    const int t = threadIdx.x;                 // 1024 threads
    __shared__ int wsum[32];

    int mynz = 0;
#pragma unroll
    for (int k = 0; k < 4; k++) {
        int i = t * 4 + k;
        if ((i & 3) && mraw[i]) mynz = 1;
    }
    const int is_u8 = __syncthreads_or(mynz);  // bool-as-u8 vs bool-as-i32

    int m0, m1;
    if (is_u8) {
        m0 = mraw[b * 2048 + 2 * t];
        m1 = mraw[b * 2048 + 2 * t + 1];
    } else {
        const int* mi = (const int*)mraw;
        m0 = mi[b * 2048 + 2 * t];
        m1 = mi[b * 2048 + 2 * t + 1];
    }
    const int f0 = (m0 == 0), f1 = (m1 == 0);
    const int pair = f0 + f1;
    const int lane = t & 31, w = t >> 5;

    int sc = pair;
#pragma unroll
    for (int d = 1; d < 32; d <<= 1) {
        int v = __shfl_up_sync(0xffffffffu, sc, d);
        if (lane >= d) sc += v;
    }
    if (lane == 31) wsum[w] = sc;
    __syncthreads();
    if (w == 0) {
        int s2 = wsum[lane];
#pragma unroll
        for (int d = 1; d < 32; d <<= 1) {
            int u = __shfl_up_sync(0xffffffffu, s2, d);
            if (lane >= d) s2 += u;
        }
        wsum[lane] = s2;
    }
    __syncthreads();
    int base = (w ? wsum[w - 1] : 0) + sc - pair;
    if (f0) g_idx[b][base++] = 2 * t;
    if (f1) g_idx[b][base] = 2 * t + 1;
    if (t == 0) g_cnt[b] = wsum[31];
}

// ---- helpers ----
__device__ __forceinline__ uint32_t smem_u32(const void* p) {
    uint32_t a;
    asm("{ .reg .u64 t; cvta.to.shared.u64 t, %1; cvt.u32.u64 %0, t; }" : "=r"(a) : "l"(p));
    return a;
}
// pack (a -> low half, b -> high half): bf16 hi + bf16 residual lo
__device__ __forceinline__ void split2(float a, float b, uint32_t& hi, uint32_t& lo) {
    uint32_t h;
    asm("cvt.rn.bf16x2.f32 %0, %1, %2;" : "=r"(h) : "f"(b), "f"(a));
    float ah = __uint_as_float(h << 16);
    float bh = __uint_as_float(h & 0xffff0000u);
    asm("cvt.rn.bf16x2.f32 %0, %1, %2;" : "=r"(lo) : "f"(b - bh), "f"(a - ah));
    hi = h;
}
__device__ __forceinline__ void mma_bf16(float* d, const uint32_t* a, const uint32_t* b) {
    asm volatile("mma.sync.aligned.m16n8k16.row.col.f32.bf16.bf16.f32 "
                 "{%0,%1,%2,%3}, {%4,%5,%6,%7}, {%8,%9}, {%0,%1,%2,%3};"
                 : "+f"(d[0]), "+f"(d[1]), "+f"(d[2]), "+f"(d[3])
                 : "r"(a[0]), "r"(a[1]), "r"(a[2]), "r"(a[3]), "r"(b[0]), "r"(b[1]));
}
__device__ __forceinline__ void ldsm2(uint32_t& r0, uint32_t& r1, uint32_t addr) {
    asm volatile("ldmatrix.sync.aligned.m8n8.x2.shared.b16 {%0,%1}, [%2];"
                 : "=r"(r0), "=r"(r1) : "r"(addr));
}
__device__ __forceinline__ void ldsm2t(uint32_t& r0, uint32_t& r1, uint32_t addr) {
    asm volatile("ldmatrix.sync.aligned.m8n8.x2.trans.shared.b16 {%0,%1}, [%2];"
                 : "=r"(r0), "=r"(r1) : "r"(addr));
}
__device__ __forceinline__ void ldsm4(uint32_t* r, uint32_t addr) {
    asm volatile("ldmatrix.sync.aligned.m8n8.x4.shared.b16 {%0,%1,%2,%3}, [%4];"
                 : "=r"(r[0]), "=r"(r[1]), "=r"(r[2]), "=r"(r[3]) : "r"(addr));
}

// ---- pass 2: gather + convert K/V to bf16 hi/lo in compacted order ----
__global__ void __launch_bounds__(256)
convert_kv(const float* __restrict__ K, const float* __restrict__ V)
{
    const int bh = blockIdx.y, b = bh >> 3;
    const int slot = blockIdx.x * 16 + (threadIdx.x >> 4);
    const int c4 = (threadIdx.x & 15) << 2;
    const size_t doff = ((((size_t)bh << 11) + slot) << 7) + c4 * 2;  // byte offset
    uint32_t kh0 = 0, kl0 = 0, kh1 = 0, kl1 = 0;
    uint32_t vh0 = 0, vl0 = 0, vh1 = 0, vl1 = 0;
    if (slot < g_cnt[b]) {
        const int row = g_idx[b][slot];
        const float4 kk = *(const float4*)(K + ((((size_t)bh << 11) + row) << 6) + c4);
        const float4 vv = *(const float4*)(V + ((((size_t)bh << 11) + row) << 6) + c4);
        split2(kk.x, kk.y, kh0, kl0); split2(kk.z, kk.w, kh1, kl1);
        split2(vv.x, vv.y, vh0, vl0); split2(vv.z, vv.w, vh1, vl1);
    }
    *(uint2*)(KCH + doff) = make_uint2(kh0, kh1);
    *(uint2*)(KCL + doff) = make_uint2(kl0, kl1);
    *(uint2*)(VCH + doff) = make_uint2(vh0, vh1);
    *(uint2*)(VCL + doff) = make_uint2(vl0, vl1);
}

// ---- cp.async staging of one 64-key tile (K/V hi/lo) into a smem stage ----
__device__ __forceinline__ void stage_tile(uint32_t sdst, int bh, int kv0, int tid)
{
#pragma unroll
    for (int it = 0; it < 8; it++) {
        const int tensor = it >> 1;                      // compile-time
        const int cc = ((it & 1) << 8) + tid;            // 0..511
        const int r = cc >> 3, ch = cc & 7;
        const unsigned char* g = (tensor == 0) ? KCH : (tensor == 1) ? KCL
                               : (tensor == 2) ? VCH : VCL;
        const unsigned char* src = g + ((((size_t)bh << 11) + kv0 + r) << 7) + (ch << 4);
        uint32_t dst = sdst + tensor * 8192 + r * 128 + ((ch ^ (r & 7)) << 4);
        asm volatile("cp.async.cg.shared.global [%0], [%1], 16;"
                     :: "r"(dst), "l"(src) : "memory");
    }
}
#define CP_COMMIT() asm volatile("cp.async.commit_group;" ::: "memory")
#define CP_WAIT0()  asm volatile("cp.async.wait_group 0;" ::: "memory")

// ---- main kernel: 256 threads, 8 warps, 128 q-rows per CTA ----
__global__ void __launch_bounds__(256, 2)
attn_mma(const float* __restrict__ Q, float* __restrict__ out)
{
    extern __shared__ char smem[];
    const uint32_t sb = smem_u32(smem);

    const int tid  = threadIdx.x;
    const int warp = tid >> 5;
    const int lane = tid & 31;
    const int gid  = lane >> 2;
    const int tig  = lane & 3;
    const int R0   = warp << 4;

    const int bh = blockIdx.y;
    const int b  = bh >> 3;
    const int q0 = blockIdx.x << 7;      // 128-row q tile

    const int cnt    = g_cnt[b];
    const int ntiles = (cnt + 63) >> 6;

    const float* Qg = Q + ((((size_t)bh << 11) + q0) << 6);

    // stage tile 0 first (overlaps with Q conversion below)
    stage_tile(sb + SM_KV, bh, 0, tid);
    CP_COMMIT();

    // ---- Q -> smem (hi/lo bf16, XOR swizzle) ----
#pragma unroll
    for (int it = 0; it < 8; it++) {
        int idx = it * 256 + tid;        // 2048 float4 slots: 128 rows x 16
        int r   = idx >> 4;
        int c4  = (idx & 15) << 2;
        float4 v = *(const float4*)(Qg + (r << 6) + c4);
        uint32_t h0, l0, h1, l1;
        split2(v.x, v.y, h0, l0);
        split2(v.z, v.w, h1, l1);
        uint32_t off = r * 128 + ((c4 * 2) ^ ((r & 7) << 4));
        *(uint2*)(smem + SM_QHI + off) = make_uint2(h0, h1);
        *(uint2*)(smem + SM_QLO + off) = make_uint2(l0, l1);
    }
    __syncthreads();

    // ---- Q A-fragments in registers for the whole kernel ----
    uint32_t qh[4][4], ql[4][4];
    {
        const int arow = R0 + (lane & 7) + ((lane >> 3) & 1) * 8;
        const int asw  = lane & 7;
#pragma unroll
        for (int kk = 0; kk < 4; kk++) {
            uint32_t off = arow * 128 + ((((2 * kk + (lane >> 4)) ^ asw)) << 4);
            ldsm4(qh[kk], sb + SM_QHI + off);
            ldsm4(ql[kk], sb + SM_QLO + off);
        }
    }

    float o[8][4];
#pragma unroll
    for (int j = 0; j < 8; j++)
#pragma unroll
        for (int e = 0; e < 4; e++) o[j][e] = 0.0f;
    float lsum_lo = 0.0f, lsum_hi = 0.0f;

    const int krow = lane & 7;
    const int ksel = (lane >> 3) & 1;
    const int vrow = (lane & 7) + ((lane >> 3) & 1) * 8;

    for (int kt = 0; kt < ntiles; kt++) {
        CP_WAIT0();
        __syncthreads();                 // tile kt visible; old buffer free
        if (kt + 1 < ntiles) {
            stage_tile(sb + SM_KV + ((kt + 1) & 1) * STAGE, bh, (kt + 1) << 6, tid);
            CP_COMMIT();
        }
        const uint32_t kb = sb + SM_KV + (kt & 1) * STAGE;  // KHI|KLO|VHI|VLO

        // ---- S = Q K^T (3-pass split) ----
        float s[8][4];
#pragma unroll
        for (int j = 0; j < 8; j++) {
#pragma unroll
            for (int e = 0; e < 4; e++) s[j][e] = 0.0f;
#pragma unroll
            for (int kk = 0; kk < 4; kk++) {
                const int rr = 8 * j + krow;
                uint32_t off = rr * 128 + (((2 * kk + ksel) ^ krow) << 4);
                uint32_t kbh[2], kbl[2];
                ldsm2(kbh[0], kbh[1], kb + off);
                ldsm2(kbl[0], kbl[1], kb + 8192 + off);
                mma_bf16(s[j], qh[kk], kbh);
                mma_bf16(s[j], qh[kk], kbl);
                mma_bf16(s[j], ql[kk], kbh);
            }
        }

        // ---- softmax: p = exp(10*tanh(s/8) - 10); padded keys give e^-10*V0=0 ----
#pragma unroll
        for (int j = 0; j < 8; j++) {
#pragma unroll
            for (int e = 0; e < 4; e++) {
                float eu = __expf(0.25f * s[j][e]);
                float p  = __expf(-__fdividef(20.0f, eu + 1.0f));
                s[j][e] = p;
                if ((e & 2) == 0) lsum_lo += p; else lsum_hi += p;
            }
        }

        // ---- O += P V (3-pass split) ----
#pragma unroll
        for (int kk = 0; kk < 4; kk++) {
            const int j0 = 2 * kk;
            uint32_t pah[4], pal[4];
            split2(s[j0][0],     s[j0][1],     pah[0], pal[0]);
            split2(s[j0][2],     s[j0][3],     pah[1], pal[1]);
            split2(s[j0 + 1][0], s[j0 + 1][1], pah[2], pal[2]);
            split2(s[j0 + 1][2], s[j0 + 1][3], pah[3], pal[3]);
#pragma unroll
            for (int j = 0; j < 8; j++) {
                const int rr = 16 * kk + vrow;
                uint32_t off = rr * 128 + ((j ^ (vrow & 7)) << 4);
                uint32_t vbh[2], vbl[2];
                ldsm2t(vbh[0], vbh[1], kb + 16384 + off);
                ldsm2t(vbl[0], vbl[1], kb + 24576 + off);
                mma_bf16(o[j], pah, vbh);
                mma_bf16(o[j], pah, vbl);
                mma_bf16(o[j], pal, vbh);
            }
        }
    }

    // ---- epilogue ----
    lsum_lo += __shfl_xor_sync(0xffffffffu, lsum_lo, 1);
    lsum_lo += __shfl_xor_sync(0xffffffffu, lsum_lo, 2);
    lsum_hi += __shfl_xor_sync(0xffffffffu, lsum_hi, 1);
    lsum_hi += __shfl_xor_sync(0xffffffffu, lsum_hi, 2);
    const float inv_lo = 1.0f / lsum_lo;
    const float inv_hi = 1.0f / lsum_hi;

    const size_t row_lo = ((size_t)bh << 11) + q0 + R0 + gid;
    const size_t row_hi = row_lo + 8;
#pragma unroll
    for (int j = 0; j < 8; j++) {
        int col = 8 * j + 2 * tig;
        *(float2*)(out + row_lo * 64 + col) = make_float2(o[j][0] * inv_lo, o[j][1] * inv_lo);
        *(float2*)(out + row_hi * 64 + col) = make_float2(o[j][2] * inv_hi, o[j][3] * inv_hi);
    }
}

extern "C" void kernel_launch(void* const* d_in, const int* in_sizes, int n_in,
                              void* d_out, int out_size)
{
    const float* Q = (const float*)d_in[0];
    const float* K = (const float*)d_in[1];
    const float* V = (const float*)d_in[2];
    const unsigned char* mraw = (const unsigned char*)d_in[3];
    float* out = (float*)d_out;

    build_idx<<<8, 1024>>>(mraw);
    {
        dim3 g(128, 64);
        convert_kv<<<g, 256>>>(K, V);
    }
    cudaFuncSetAttribute(attn_mma, cudaFuncAttributeMaxDynamicSharedMemorySize, SM_TOTAL);
    dim3 grid(16, 64);                   // (q tiles of 128, B*H)
    attn_mma<<<grid, 256, SM_TOTAL>>>(Q, out);
}